// round 5
// baseline (speedup 1.0000x reference)
#include <cuda_runtime.h>
#include <math.h>
#include <stdint.h>

typedef unsigned long long u64;

static constexpr int B_  = 4;
static constexpr int L_  = 1024;
static constexpr int D_  = 768;
static constexpr int H_  = 12;
static constexpr int HD_ = 64;
static constexpr int TQ_ = 64;
static constexpr int TK_ = 128;
static constexpr int NCH_ = L_ / TK_;   // 8

// attn dynamic smem: max(pass1: Qsd 64*64 u64 + Ks 64*132 f32,
//                        pass2: Esd 128*66 u64 + Vs 128*68 f32)
static constexpr int DYN_SMEM_BYTES = 128*66*8 + 128*68*4;   // 102400

// ---------------- packed f32x2 helpers ----------------
__device__ __forceinline__ u64 pack2(float v) {
    u64 r; asm("mov.b64 %0, {%1, %1};" : "=l"(r) : "f"(v)); return r;
}
__device__ __forceinline__ void fma2(u64& c, u64 a, u64 b) {
    asm("fma.rn.f32x2 %0, %1, %2, %0;" : "+l"(c) : "l"(a), "l"(b));
}
__device__ __forceinline__ float2 unp(u64 v) {
    float2 f; asm("mov.b64 {%0, %1}, %2;" : "=f"(f.x), "=f"(f.y) : "l"(v)); return f;
}

// ---------------- device scratch ----------------
__device__ float g_q[(size_t)B_ * L_ * D_];
__device__ float g_k[(size_t)B_ * L_ * D_];
__device__ float g_v[(size_t)B_ * L_ * D_];
__device__ float g_w[(size_t)B_ * L_ * D_];

// ---------------- SGEMM core: C[128,128] tile of A[M,768] @ W[768,768]^T ----
// micro-tile 8m x 8n, n-paired f32x2 accumulators, dup'd A in smem, no packs
// in the inner loop. Double-buffered K-tiles (Ktile=8), one sync per tile.
__device__ __forceinline__ void sgemm_128(const float* __restrict__ A,
                                          const float* __restrict__ W,
                                          const float* __restrict__ bias,
                                          float* __restrict__ C,
                                          int m0, int n0)
{
    __shared__ u64   Asd[2][8][128];
    __shared__ float Bs [2][8][132];
    const int tid  = threadIdx.x;
    const int tx   = tid & 15, ty = tid >> 4;
    const int lrow = tid >> 1;
    const int lk4  = (tid & 1) * 4;

    const float* Ap = A + (size_t)(m0 + lrow) * D_ + lk4;
    const float* Wp = W + (size_t)(n0 + lrow) * D_ + lk4;

    u64 acc[8][2][2] = {};   // [m i][n-half g][pair]

    float4 av = *(const float4*)Ap;
    float4 wv = *(const float4*)Wp;
    Asd[0][lk4+0][lrow] = pack2(av.x); Asd[0][lk4+1][lrow] = pack2(av.y);
    Asd[0][lk4+2][lrow] = pack2(av.z); Asd[0][lk4+3][lrow] = pack2(av.w);
    Bs [0][lk4+0][lrow] = wv.x;        Bs [0][lk4+1][lrow] = wv.y;
    Bs [0][lk4+2][lrow] = wv.z;        Bs [0][lk4+3][lrow] = wv.w;
    __syncthreads();

    const int NT = D_ / 8;   // 96
    for (int kt = 0; kt < NT; kt++) {
        const int s = kt & 1;
        if (kt + 1 < NT) {
            av = *(const float4*)(Ap + (kt + 1) * 8);
            wv = *(const float4*)(Wp + (kt + 1) * 8);
        }
        #pragma unroll
        for (int kk = 0; kk < 8; kk++) {
            u64 a[8];
            #pragma unroll
            for (int i = 0; i < 8; i++) a[i] = Asd[s][kk][ty*8 + i];
            ulonglong2 b0 = *(const ulonglong2*)&Bs[s][kk][4*tx];
            ulonglong2 b1 = *(const ulonglong2*)&Bs[s][kk][64 + 4*tx];
            #pragma unroll
            for (int i = 0; i < 8; i++) {
                fma2(acc[i][0][0], a[i], b0.x);
                fma2(acc[i][0][1], a[i], b0.y);
                fma2(acc[i][1][0], a[i], b1.x);
                fma2(acc[i][1][1], a[i], b1.y);
            }
        }
        if (kt + 1 < NT) {
            const int s2 = s ^ 1;
            Asd[s2][lk4+0][lrow] = pack2(av.x); Asd[s2][lk4+1][lrow] = pack2(av.y);
            Asd[s2][lk4+2][lrow] = pack2(av.z); Asd[s2][lk4+3][lrow] = pack2(av.w);
            Bs [s2][lk4+0][lrow] = wv.x;        Bs [s2][lk4+1][lrow] = wv.y;
            Bs [s2][lk4+2][lrow] = wv.z;        Bs [s2][lk4+3][lrow] = wv.w;
        }
        __syncthreads();
    }

    #pragma unroll
    for (int i = 0; i < 8; i++) {
        const int r = m0 + ty*8 + i;
        #pragma unroll
        for (int g = 0; g < 2; g++) {
            const int c = n0 + g*64 + 4*tx;
            float2 u0 = unp(acc[i][g][0]);
            float2 u1 = unp(acc[i][g][1]);
            float4 o = make_float4(u0.x, u0.y, u1.x, u1.y);
            if (bias) {
                o.x += bias[c+0]; o.y += bias[c+1];
                o.z += bias[c+2]; o.w += bias[c+3];
            }
            *(float4*)&C[(size_t)r * D_ + c] = o;
        }
    }
}

__global__ __launch_bounds__(256, 2)
void sgemm_qkv_kernel(const float* __restrict__ Aq, const float* __restrict__ Ak,
                      const float* __restrict__ Av,
                      const float* __restrict__ Wq, const float* __restrict__ Wk,
                      const float* __restrict__ Wv,
                      float* __restrict__ Cq, float* __restrict__ Ck,
                      float* __restrict__ Cv)
{
    const int sel = blockIdx.x / 6;
    const int n0  = (blockIdx.x % 6) * 128;
    const int m0  = blockIdx.y * 128;
    const float* A = (sel == 0) ? Aq : (sel == 1) ? Ak : Av;
    const float* W = (sel == 0) ? Wq : (sel == 1) ? Wk : Wv;
    float*       C = (sel == 0) ? Cq : (sel == 1) ? Ck : Cv;
    sgemm_128(A, W, nullptr, C, m0, n0);
}

__global__ __launch_bounds__(256, 2)
void sgemm_proj_kernel(const float* __restrict__ A, const float* __restrict__ W,
                       const float* __restrict__ bias, float* __restrict__ C)
{
    sgemm_128(A, W, bias, C, blockIdx.y * 128, blockIdx.x * 128);
}

// ---------------- fused relative-position attention ----------------------
// One block per (b, h, 64-query-row tile). 256 threads, 2 blocks/SM.
// Logits stored pre-scaled by 8*log2(e); exp via exp2f.
__global__ __launch_bounds__(256, 2)
void attn_kernel(const float* __restrict__ gq, const float* __restrict__ gk,
                 const float* __restrict__ gv,
                 const float* __restrict__ relk, const float* __restrict__ relv,
                 float* __restrict__ attn, float* __restrict__ gw)
{
    extern __shared__ float dsm[];
    // pass1 views
    u64*   Qsd = (u64*)dsm;            // [64][64]  dup'd, d-major
    float* Ks  = dsm + 16384/2;        // [64][132] d-major (offset 8192 floats)
    // pass2 views (overlap)
    u64*   Esd = (u64*)dsm;            // [128][66] dup'd, k-major
    float* Vs  = dsm + 16896;          // [128][68] row-major

    __shared__ float sh_relk[7*HD_];
    __shared__ float sh_relv[7*HD_];
    __shared__ float sh_bias[TQ_*7];
    __shared__ float sh_rowmax[TQ_];
    __shared__ float sh_T[TQ_];
    __shared__ float sh_S0[TQ_];
    __shared__ float sh_S6[TQ_];
    __shared__ float sh_pmid[TQ_*5];

    const int q0  = blockIdx.x * TQ_;
    const int h   = blockIdx.y;
    const int b   = blockIdx.z;
    const int tid = threadIdx.x;
    const int tx  = tid & 15, ty = tid >> 4;

    const float CSC = 8.f * 1.44269504088896340736f;   // 8 * log2(e)

    for (int i = tid; i < 7*HD_; i += 256) { sh_relk[i] = relk[i]; sh_relv[i] = relv[i]; }
    for (int i = tid; i < TQ_*5; i += 256) sh_pmid[i] = 0.f;

    const float* qbase = gq + ((size_t)(b*L_ + q0))*D_ + h*HD_;
    const float* kbase = gk + ((size_t)b*L_)*D_ + h*HD_;
    const float* vbase = gv + ((size_t)b*L_)*D_ + h*HD_;
    float* attn_base = attn + (((size_t)(b*H_ + h))*L_ + q0) * L_;

    // ---- Q load, transposed + dup'd: Qsd[d][m] = {q,q} ----
    {
        const int lm = tid >> 2;          // 0..63 (m)
        const int d0 = (tid & 3) * 4;
        #pragma unroll
        for (int r = 0; r < 4; r++) {
            int d = d0 + 16*r;
            float4 v = *(const float4*)(qbase + (size_t)lm*D_ + d);
            Qsd[(d+0)*64 + lm] = pack2(v.x);
            Qsd[(d+1)*64 + lm] = pack2(v.y);
            Qsd[(d+2)*64 + lm] = pack2(v.z);
            Qsd[(d+3)*64 + lm] = pack2(v.w);
        }
    }
    __syncthreads();

    // ---- rel-k bias: bias[m][r] = Q[m] . rel_k[r]  (unscaled) ----
    for (int idx = tid; idx < TQ_*7; idx += 256) {
        int m = idx / 7, rr = idx % 7;
        float s = 0.f;
        #pragma unroll
        for (int d = 0; d < HD_; d++)
            s = fmaf(*(const float*)&Qsd[d*64 + m], sh_relk[rr*HD_ + d], s);
        sh_bias[idx] = s;
    }
    __syncthreads();

    float pmax[4] = {-1e30f, -1e30f, -1e30f, -1e30f};

    // ================= pass 1: logits (pre-scaled by 8*log2e) =================
    for (int kc = 0; kc < NCH_; kc++) {
        const int k0 = kc * TK_;
        // K loader: plain transposed f32 into Ks[d][n]
        {
            const int ln  = tid >> 1;
            const int dk0 = (tid & 1) * 4;
            #pragma unroll
            for (int r = 0; r < 8; r++) {
                int d = dk0 + 8*r;
                float4 v = *(const float4*)(kbase + (size_t)(k0 + ln)*D_ + d);
                Ks[(d+0)*132 + ln] = v.x; Ks[(d+1)*132 + ln] = v.y;
                Ks[(d+2)*132 + ln] = v.z; Ks[(d+3)*132 + ln] = v.w;
            }
        }
        __syncthreads();

        u64 acc[4][2][2] = {};   // [m i][n-half g][pair]
        #pragma unroll 8
        for (int d = 0; d < HD_; d++) {
            u64 a[4];
            #pragma unroll
            for (int i = 0; i < 4; i++) a[i] = Qsd[d*64 + ty*4 + i];
            ulonglong2 b0 = *(const ulonglong2*)&Ks[d*132 + 4*tx];
            ulonglong2 b1 = *(const ulonglong2*)&Ks[d*132 + 64 + 4*tx];
            #pragma unroll
            for (int i = 0; i < 4; i++) {
                fma2(acc[i][0][0], a[i], b0.x);
                fma2(acc[i][0][1], a[i], b0.y);
                fma2(acc[i][1][0], a[i], b1.x);
                fma2(acc[i][1][1], a[i], b1.y);
            }
        }

        #pragma unroll
        for (int i = 0; i < 4; i++) {
            const int m  = ty*4 + i;
            const int qg = q0 + m;
            const float* brow = &sh_bias[m*7];
            #pragma unroll
            for (int g = 0; g < 2; g++) {
                float2 u0 = unp(acc[i][g][0]);
                float2 u1 = unp(acc[i][g][1]);
                float vv[4] = {u0.x, u0.y, u1.x, u1.y};
                float o[4];
                #pragma unroll
                for (int c = 0; c < 4; c++) {
                    int kg  = k0 + g*64 + 4*tx + c;
                    int dlt = kg - qg;
                    int rr  = dlt < -3 ? 0 : (dlt > 3 ? 6 : dlt + 3);
                    float s = CSC * (vv[c] + brow[rr]);
                    o[c] = s;
                    pmax[i] = fmaxf(pmax[i], s);
                }
                *(float4*)(attn_base + (size_t)m*L_ + k0 + g*64 + 4*tx)
                    = make_float4(o[0], o[1], o[2], o[3]);
            }
        }
        __syncthreads();
    }

    // ---- row-max reduce across the 16 tx lanes ----
    #pragma unroll
    for (int i = 0; i < 4; i++) {
        float v = pmax[i];
        #pragma unroll
        for (int off = 8; off > 0; off >>= 1)
            v = fmaxf(v, __shfl_xor_sync(0xffffffffu, v, off));
        if (tx == 0) sh_rowmax[ty*4 + i] = v;
    }
    __syncthreads();

    // ================= pass 2: exp + sums + PV =================
    const int m2  = tid >> 2;        // exp-stage row
    const int q4  = tid & 3;
    const int qg2 = q0 + m2;
    const float rm2 = sh_rowmax[m2];

    const int txd = tid & 15;        // PV: d = 4*txd + c
    const int tym = tid >> 4;        // PV: m = tym*4 + i

    float tsum = 0.f, s0sum = 0.f, s6sum = 0.f;
    u64 acc2[4][2] = {};             // [m i][d-pair]

    for (int kc = 0; kc < NCH_; kc++) {
        const int k0 = kc * TK_;
        // V loader: direct row-major copy (d contiguous)
        {
            const int lnv = tid >> 1;
            const int dv0 = (tid & 1) * 4;
            #pragma unroll
            for (int r = 0; r < 8; r++) {
                int d = dv0 + 8*r;
                float4 v = *(const float4*)(vbase + (size_t)(k0 + lnv)*D_ + d);
                *(float4*)&Vs[lnv*68 + d] = v;
            }
        }
        // exp stage: thread owns row m2, cols q4*4 + 16r
        #pragma unroll
        for (int r = 0; r < 8; r++) {
            int c = q4*4 + 16*r;
            float4 sv = *(const float4*)(attn_base + (size_t)m2*L_ + k0 + c);
            float svv[4] = {sv.x, sv.y, sv.z, sv.w};
            #pragma unroll
            for (int j = 0; j < 4; j++) {
                float e = exp2f(svv[j] - rm2);
                tsum += e;
                int dlt = k0 + c + j - qg2;
                if (dlt <= -3)      s0sum += e;
                else if (dlt >= 3)  s6sum += e;
                else                sh_pmid[m2*5 + dlt + 2] = e;
                Esd[(c+j)*66 + m2] = pack2(e);
            }
        }
        __syncthreads();
        // PV: E broadcast (dup'd), V natural d-pairs
        #pragma unroll 8
        for (int k = 0; k < TK_; k++) {
            u64 e[4];
            #pragma unroll
            for (int i = 0; i < 4; i++) e[i] = Esd[k*66 + tym*4 + i];
            ulonglong2 v01 = *(const ulonglong2*)&Vs[k*68 + 4*txd];
            #pragma unroll
            for (int i = 0; i < 4; i++) {
                fma2(acc2[i][0], e[i], v01.x);
                fma2(acc2[i][1], e[i], v01.y);
            }
        }
        __syncthreads();
    }

    // ---- row-sum reduce over the 4 q4 lanes ----
    tsum  += __shfl_xor_sync(0xffffffffu, tsum,  1);
    tsum  += __shfl_xor_sync(0xffffffffu, tsum,  2);
    s0sum += __shfl_xor_sync(0xffffffffu, s0sum, 1);
    s0sum += __shfl_xor_sync(0xffffffffu, s0sum, 2);
    s6sum += __shfl_xor_sync(0xffffffffu, s6sum, 1);
    s6sum += __shfl_xor_sync(0xffffffffu, s6sum, 2);
    if (q4 == 0) { sh_T[m2] = tsum; sh_S0[m2] = s0sum; sh_S6[m2] = s6sum; }
    __syncthreads();

    // ---- w = (w1 + w2) * invT -> scratch [B,L,H,hd] ----
    {
        float* wbase = gw + ((size_t)(b*L_ + q0))*D_ + h*HD_;
        #pragma unroll
        for (int i = 0; i < 4; i++) {
            const int m = tym*4 + i;
            float T  = sh_T[m];
            float S0 = sh_S0[m];
            float S6 = sh_S6[m];
            float inv = 1.f / T;
            float mids[5];
            #pragma unroll
            for (int rr = 0; rr < 5; rr++) mids[rr] = sh_pmid[m*5 + rr];
            float2 u0 = unp(acc2[i][0]);
            float2 u1 = unp(acc2[i][1]);
            float vals[4] = {u0.x, u0.y, u1.x, u1.y};
            float o[4];
            #pragma unroll
            for (int c = 0; c < 4; c++) {
                int d = 4*txd + c;
                float w2 = S0 * sh_relv[d] + S6 * sh_relv[6*HD_ + d];
                #pragma unroll
                for (int rr = 0; rr < 5; rr++)
                    w2 = fmaf(mids[rr], sh_relv[(rr+1)*HD_ + d], w2);
                o[c] = (vals[c] + w2) * inv;
            }
            *(float4*)(wbase + (size_t)m*D_ + 4*txd) = make_float4(o[0], o[1], o[2], o[3]);
        }
    }

    // ================= pass 3: normalized attn out =================
    const float inv3 = 1.f / sh_T[m2];
    #pragma unroll 4
    for (int r = 0; r < 64; r++) {
        int c = q4*4 + 16*r;
        float* p = attn_base + (size_t)m2*L_ + c;
        float4 a = *(const float4*)p;
        a.x = exp2f(a.x - rm2) * inv3;
        a.y = exp2f(a.y - rm2) * inv3;
        a.z = exp2f(a.z - rm2) * inv3;
        a.w = exp2f(a.w - rm2) * inv3;
        *(float4*)p = a;
    }
}

// ---------------- launch ----------------
extern "C" void kernel_launch(void* const* d_in, const int* in_sizes, int n_in,
                              void* d_out, int out_size)
{
    const float* query  = (const float*)d_in[0];
    const float* key    = (const float*)d_in[1];
    const float* value  = (const float*)d_in[2];
    const float* Wq     = (const float*)d_in[3];
    const float* Wk     = (const float*)d_in[4];
    const float* Wv     = (const float*)d_in[5];
    const float* Wproj  = (const float*)d_in[6];
    const float* b_proj = (const float*)d_in[7];
    const float* relk   = (const float*)d_in[8];
    const float* relv   = (const float*)d_in[9];

    float* out  = (float*)d_out;
    float* attn = out + (size_t)B_ * L_ * D_;   // x first, then attn

    float *gq, *gk, *gv, *gw;
    cudaGetSymbolAddress((void**)&gq, g_q);
    cudaGetSymbolAddress((void**)&gk, g_k);
    cudaGetSymbolAddress((void**)&gv, g_v);
    cudaGetSymbolAddress((void**)&gw, g_w);

    cudaFuncSetAttribute(attn_kernel, cudaFuncAttributeMaxDynamicSharedMemorySize,
                         DYN_SMEM_BYTES);

    sgemm_qkv_kernel<<<dim3(18, 32), 256>>>(query, key, value, Wq, Wk, Wv, gq, gk, gv);

    attn_kernel<<<dim3(L_/TQ_, H_, B_), 256, DYN_SMEM_BYTES>>>(
        gq, gk, gv, relk, relv, attn, gw);

    sgemm_proj_kernel<<<dim3(6, 32), 256>>>(gw, Wproj, b_proj, out);
}